// round 14
// baseline (speedup 1.0000x reference)
#include <cuda_runtime.h>
#include <math.h>
#include <stdint.h>

// RandomizedOscillatorsNetwork: B=128, T=1024, I=64, H=512
// 16 clusters x 8 CTAs; cluster owns 8 batch rows; CTA owns 64 H-cols, weight slice
// (h2h||x2h) [576x64] resident in SMEM.
// Exchange: per-thread st.async.shared::cluster with mbarrier complete_tx — each thread
// pushes its hy pair (8B) to all 8 CTAs (incl self) straight from registers; x(t+1)
// self-pushed the same way. One unified vbx[2][576][8] operand buffer, ONE GEMM pass,
// ONE __syncthreads per step. NT=256: warp = 72-k slice, lane = 2 cols, batch pairs
// packed fma.rn.f32x2; split-K partials double-buffered in smem.

#define DTc 0.042f
#define Bn 128
#define Tn 1024
#define In 64
#define Hn 512
#define NT 256

#define W_BYTES    (576*64*4)              // 147456
#define VBX_OFF    W_BYTES                 // vbx[2][576][8] floats (rows 0..511 hy, 512..575 x)
#define VBX_BYTES  (2*576*8*4)             // 36864
#define RF_OFF     (VBX_OFF + VBX_BYTES)   // rf[2][8 warps][8 b][64 col]
#define RF_BYTES   (2*8*8*64*4)            // 32768
#define MB_OFF     (RF_OFF + RF_BYTES)
#define SMEM_BYTES (MB_OFF + 64)           // 217152

#define VBUF_BYTES 18432                   // one vbx buffer (576*8*4)
#define STEP_TX    18432                   // 8*2048 hy + 2048 x per phase

typedef unsigned long long u64;

__device__ __forceinline__ u64 pack2(float lo, float hi) {
    u64 r; asm("mov.b64 %0, {%1, %2};" : "=l"(r) : "f"(lo), "f"(hi)); return r;
}
__device__ __forceinline__ void unpack2(u64 v, float& lo, float& hi) {
    asm("mov.b64 {%0, %1}, %2;" : "=f"(lo), "=f"(hi) : "l"(v));
}
__device__ __forceinline__ u64 ffma2(u64 a, u64 b, u64 c) {
    u64 d; asm("fma.rn.f32x2 %0, %1, %2, %3;" : "=l"(d) : "l"(a), "l"(b), "l"(c)); return d;
}
__device__ __forceinline__ uint32_t smem_u32(const void* p) {
    uint32_t a; asm("{ .reg .u64 t; cvta.to.shared.u64 t, %1; cvt.u32.u64 %0, t; }"
                    : "=r"(a) : "l"(p)); return a;
}
__device__ __forceinline__ uint32_t mapa_u32(uint32_t addr, int rank) {
    uint32_t r; asm("mapa.shared::cluster.u32 %0, %1, %2;" : "=r"(r) : "r"(addr), "r"(rank));
    return r;
}
__device__ __forceinline__ void mbar_init(uint32_t mbar, uint32_t cnt) {
    asm volatile("mbarrier.init.shared.b64 [%0], %1;" :: "r"(mbar), "r"(cnt) : "memory");
}
__device__ __forceinline__ void mbar_expect(uint32_t mbar, uint32_t tx) {
    asm volatile("mbarrier.arrive.expect_tx.shared.b64 _, [%0], %1;" :: "r"(mbar), "r"(tx) : "memory");
}
__device__ __forceinline__ void mbar_wait(uint32_t mbar, uint32_t parity) {
    asm volatile(
        "{\n\t.reg .pred P1;\n"
        "W_%=:\n\t"
        "mbarrier.try_wait.parity.acquire.cta.shared::cta.b64 P1, [%0], %1, 0x989680;\n\t"
        "@P1 bra.uni D_%=;\n\t"
        "bra.uni W_%=;\n"
        "D_%=:\n\t}"
        :: "r"(mbar), "r"(parity) : "memory");
}
// remote (cluster-mapped) 8B store with tx accounting on the destination CTA's mbarrier
__device__ __forceinline__ void st_async_b64(uint32_t dst, u64 val, uint32_t rmbar) {
    asm volatile(
        "st.async.shared::cluster.mbarrier::complete_tx::bytes.b64 [%0], %1, [%2];"
        :: "r"(dst), "l"(val), "r"(rmbar) : "memory");
}

#define GEMM8(hA, hB, wv)                                              \
    {   u64 w0 = pack2((wv).x, (wv).x), w1 = pack2((wv).y, (wv).y);    \
        a00 = ffma2((hA).x, w0, a00); a01 = ffma2((hA).x, w1, a01);    \
        a10 = ffma2((hA).y, w0, a10); a11 = ffma2((hA).y, w1, a11);    \
        a20 = ffma2((hB).x, w0, a20); a21 = ffma2((hB).x, w1, a21);    \
        a30 = ffma2((hB).y, w0, a30); a31 = ffma2((hB).y, w1, a31); }

__global__ __launch_bounds__(NT, 1) __cluster_dims__(8, 1, 1)
void ron_kernel(const float* __restrict__ x, const float* __restrict__ x2h,
                const float* __restrict__ h2h, const float* __restrict__ bias,
                const float* __restrict__ gam, const float* __restrict__ eps,
                float* __restrict__ out, long long out_elems)
{
    extern __shared__ char smem[];
    float* W   = (float*)smem;                 // [576][64] global-k order (512..575 = x2h)
    float* vbx = (float*)(smem + VBX_OFF);     // [2][576][8]
    float* rf  = (float*)(smem + RF_OFF);      // [2][8][8][64]
    const uint32_t sbase = smem_u32(smem);
    const uint32_t mbar  = sbase + MB_OFF;

    const int tid  = threadIdx.x;
    const int cl   = blockIdx.x >> 3;
    const int rank = blockIdx.x & 7;
    const int c0   = rank * 64;
    const int b0   = cl * 8;

    // prologue: resident weight slice
    for (int idx = tid; idx < 576*64; idx += NT) {
        int k = idx >> 6, j = idx & 63;
        W[idx] = (k < Hn) ? h2h[(size_t)k*Hn + c0 + j] : x2h[(size_t)(k - Hn)*Hn + c0 + j];
    }

    // epilogue mapping: thread owns (col, batches 2pr and 2pr+1)
    const int col = tid & 63, pr = tid >> 6;       // pr in 0..3
    const int bA  = 2*pr, bB = 2*pr + 1;
    const int hg  = c0 + col;
    const float bia = bias[hg], ga = gam[hg], ep = eps[hg];
    float hy0 = 0.f, hz0 = 0.f, hy1 = 0.f, hz1 = 0.f;

    // GEMM mapping: warp w 0..7 owns k-rows [72w, 72w+72); lane cg owns cols {2cg,2cg+1}
    const int w  = tid >> 5, cg = tid & 31;
    const float* Wr0 = W + (w*72)*64 + cg*2;
    float*       rw0 = rf + w*512 + cg*2;          // + (t&1)*4096 per step

    // x pointers: this thread loads x for (b0+bA, col) and (b0+bB, col)
    const float* xpA = x + ((size_t)(b0 + bA) * Tn) * In + col;
    const float* xpB = x + ((size_t)(b0 + bB) * Tn) * In + col;

    // precomputed remote push addresses (base of vbx / mbar in each CTA of the cluster)
    uint32_t dstv[8], dstm[8];
    #pragma unroll
    for (int r = 0; r < 8; r++) {
        dstv[r] = mapa_u32(sbase + VBX_OFF, r);
        dstm[r] = mapa_u32(mbar, r);
    }
    const uint32_t hyoff = (uint32_t)(hg*32 + pr*8);          // byte offset of [hg][bA]
    const uint32_t xoff  = (uint32_t)((512 + col)*32 + pr*8); // byte offset of [512+col][bA]

    // init: vbx[1] = bootstrap buffer (hy rows zero, x rows = x(0)); mbarrier
    for (int idx = tid; idx < 576*8; idx += NT) vbx[4608 + idx] = 0.f;
    __syncthreads();
    vbx[4608 + (512 + col)*8 + bA] = xpA[0];
    vbx[4608 + (512 + col)*8 + bB] = xpB[0];
    if (tid == 0) mbar_init(mbar, 1);
    __syncthreads();
    asm volatile("barrier.cluster.arrive.aligned;" ::: "memory");
    asm volatile("barrier.cluster.wait.aligned;"   ::: "memory");
    if (tid == 0) mbar_expect(mbar, STEP_TX);     // phase 0 (pushed during step 0)

    const size_t BTH = (size_t)Bn * Tn * Hn;
    const bool writeFinal = (out_elems >= (long long)(BTH + (size_t)Bn * Hn));

    for (int t = 0; t < Tn; t++) {
        // prefetch x(t+1) early (DRAM latency hidden behind the step)
        const int tn = (t + 1 < Tn) ? (t + 1) : t;
        const float xnA = xpA[(size_t)tn * In];
        const float xnB = xpB[(size_t)tn * In];

        if (t > 0) {
            mbar_wait(mbar, (t - 1) & 1);               // all 18432B of step-t operands landed
            if (t < Tn - 1 && tid == 0) mbar_expect(mbar, STEP_TX);
        }

        // ---- single GEMM pass: 72 contiguous rows of (hy||x), no branches
        u64 a00=0ull,a01=0ull,a10=0ull,a11=0ull,a20=0ull,a21=0ull,a30=0ull,a31=0ull;
        {
            const float* Wr = Wr0;
            const float* vr = vbx + ((t - 1) & 1)*4608 + (w*72)*8;
            #pragma unroll 6
            for (int kk = 0; kk < 72; kk++) {
                float2 wv = *(const float2*)(Wr + kk*64);              // conflict-free LDS.64
                const ulonglong2* hv = (const ulonglong2*)(vr + kk*8); // broadcast LDS.128 x2
                ulonglong2 hA = hv[0];
                ulonglong2 hB = hv[1];
                GEMM8(hA, hB, wv);
            }
        }

        // ---- stage split-K partials rf[t&1][w][b][col]
        {
            float* rw = rw0 + (t & 1)*4096;
            float l0,h0,l1,h1;
            unpack2(a00,l0,h0); unpack2(a01,l1,h1);
            *(float2*)(rw + 0*64) = make_float2(l0,l1);
            *(float2*)(rw + 1*64) = make_float2(h0,h1);
            unpack2(a10,l0,h0); unpack2(a11,l1,h1);
            *(float2*)(rw + 2*64) = make_float2(l0,l1);
            *(float2*)(rw + 3*64) = make_float2(h0,h1);
            unpack2(a20,l0,h0); unpack2(a21,l1,h1);
            *(float2*)(rw + 4*64) = make_float2(l0,l1);
            *(float2*)(rw + 5*64) = make_float2(h0,h1);
            unpack2(a30,l0,h0); unpack2(a31,l1,h1);
            *(float2*)(rw + 6*64) = make_float2(l0,l1);
            *(float2*)(rw + 7*64) = make_float2(h0,h1);
        }
        __syncthreads();   // the ONLY block sync per step

        // ---- reduce + oscillator update + push (per-thread, fire-and-forget)
        {
            const float* r0 = rf + (t & 1)*4096 + bA*64 + col;
            const float* r1 = r0 + 64;
            float s0 = 0.f, s1 = 0.f;
            #pragma unroll
            for (int q = 0; q < 8; q++) { s0 += r0[q*512]; s1 += r1[q*512]; }
            float th0 = tanhf(s0 + bia);
            float th1 = tanhf(s1 + bia);
            hz0 += DTc * (th0 - ga*hy0 - ep*hz0);  hy0 += DTc * hz0;
            hz1 += DTc * (th1 - ga*hy1 - ep*hz1);  hy1 += DTc * hz1;

            // outputs (coalesced within warp: consecutive col)
            size_t o0 = ((size_t)(b0 + bA) * Tn + t) * Hn + hg;
            out[o0]                    = hy0;
            out[o0 + (size_t)Tn * Hn]  = hy1;
            if (t == Tn - 1 && writeFinal) {
                out[BTH + (size_t)(b0 + bA) * Hn + hg] = hy0;
                out[BTH + (size_t)(b0 + bB) * Hn + hg] = hy1;
            }

            // push hy pair to all 8 CTAs (incl self) + x(t+1) to self, with tx accounting
            if (t < Tn - 1) {
                const uint32_t bufo = (uint32_t)((t & 1) * VBUF_BYTES);
                u64 hv = pack2(hy0, hy1);
                #pragma unroll
                for (int r = 0; r < 8; r++)
                    st_async_b64(dstv[r] + bufo + hyoff, hv, dstm[r]);
                st_async_b64(dstv[rank] + bufo + xoff, pack2(xnA, xnB), dstm[rank]);
            }
        }
        // no bottom sync: rf is double-buffered; vbx writes are mbar-ordered
    }

    // no CTA exits while peers' st.async targeting our smem may be in flight
    asm volatile("barrier.cluster.arrive.aligned;" ::: "memory");
    asm volatile("barrier.cluster.wait.aligned;"   ::: "memory");
}

extern "C" void kernel_launch(void* const* d_in, const int* in_sizes, int n_in,
                              void* d_out, int out_size) {
    const float* x    = (const float*)d_in[0];
    const float* x2h  = (const float*)d_in[1];
    const float* h2h  = (const float*)d_in[2];
    const float* bias = (const float*)d_in[3];
    const float* gam  = (const float*)d_in[4];
    const float* eps  = (const float*)d_in[5];
    float* out = (float*)d_out;
    (void)in_sizes; (void)n_in;

    cudaFuncSetAttribute(ron_kernel, cudaFuncAttributeMaxDynamicSharedMemorySize, SMEM_BYTES);
    ron_kernel<<<128, NT, SMEM_BYTES>>>(x, x2h, h2h, bias, gam, eps, out, (long long)out_size);
}

// round 15
// speedup vs baseline: 1.0268x; 1.0268x over previous
#include <cuda_runtime.h>
#include <math.h>
#include <stdint.h>

// RandomizedOscillatorsNetwork: B=128, T=1024, I=64, H=512
// 16 clusters x 8 CTAs; cluster owns 8 batch rows; CTA owns 64 H-cols, weight slice
// (h2h||x2h) [576x64] resident in SMEM.
// Exchange (R12 arch + pipelining): after sync2, warps 1..7 each engine-push the CTA's
// 2KB hy slice to rank+w. Consumer waits in TWO groups (mbarA: first-arriving 3 slices,
// mbarB: remaining 4) so late bytes are hidden behind GEMM over early slices.
// NT=256: warp = k-slice, lane = 2 cols, batch pairs packed fma.rn.f32x2.

#define DTc 0.042f
#define Bn 128
#define Tn 1024
#define In 64
#define Hn 512
#define NT 256

#define W_BYTES   (576*64*4)              // 147456
#define VB_OFF    W_BYTES                 // vbuf[2][512][8] floats (16KB each)
#define VB_BYTES  (2*512*8*4)             // 32768
#define XB_OFF    (VB_OFF + VB_BYTES)     // xbuf[64][8] floats
#define XB_BYTES  (64*8*4)                // 2048
#define RF_OFF    (XB_OFF + XB_BYTES)     // partials [8 warps][8 b][64 col]
#define RF_BYTES  (8*8*64*4)              // 16384
#define MBA_OFF   (RF_OFF + RF_BYTES)     // mbarrier A (16B)
#define MBB_OFF   (MBA_OFF + 16)          // mbarrier B
#define SMEM_BYTES (MBB_OFF + 48)         // 198720

#define SLICE_BYTES 2048                  // 64 rows x 8 batches x 4B
#define TXA (3*SLICE_BYTES)               // sources rank-1..rank-3
#define TXB (4*SLICE_BYTES)               // sources rank-4..rank-7

typedef unsigned long long u64;

__device__ __forceinline__ u64 pack2(float lo, float hi) {
    u64 r; asm("mov.b64 %0, {%1, %2};" : "=l"(r) : "f"(lo), "f"(hi)); return r;
}
__device__ __forceinline__ void unpack2(u64 v, float& lo, float& hi) {
    asm("mov.b64 {%0, %1}, %2;" : "=f"(lo), "=f"(hi) : "l"(v));
}
__device__ __forceinline__ u64 ffma2(u64 a, u64 b, u64 c) {
    u64 d; asm("fma.rn.f32x2 %0, %1, %2, %3;" : "=l"(d) : "l"(a), "l"(b), "l"(c)); return d;
}
__device__ __forceinline__ uint32_t smem_u32(const void* p) {
    uint32_t a; asm("{ .reg .u64 t; cvta.to.shared.u64 t, %1; cvt.u32.u64 %0, t; }"
                    : "=r"(a) : "l"(p)); return a;
}
__device__ __forceinline__ uint32_t mapa_u32(uint32_t addr, int rank) {
    uint32_t r; asm("mapa.shared::cluster.u32 %0, %1, %2;" : "=r"(r) : "r"(addr), "r"(rank));
    return r;
}
__device__ __forceinline__ void mbar_init(uint32_t mbar, uint32_t cnt) {
    asm volatile("mbarrier.init.shared.b64 [%0], %1;" :: "r"(mbar), "r"(cnt) : "memory");
}
__device__ __forceinline__ void mbar_expect(uint32_t mbar, uint32_t tx) {
    asm volatile("mbarrier.arrive.expect_tx.shared.b64 _, [%0], %1;" :: "r"(mbar), "r"(tx) : "memory");
}
__device__ __forceinline__ void mbar_wait(uint32_t mbar, uint32_t parity) {
    asm volatile(
        "{\n\t.reg .pred P1;\n"
        "W_%=:\n\t"
        "mbarrier.try_wait.parity.acquire.cta.shared::cta.b64 P1, [%0], %1, 0x989680;\n\t"
        "@P1 bra.uni D_%=;\n\t"
        "bra.uni W_%=;\n"
        "D_%=:\n\t}"
        :: "r"(mbar), "r"(parity) : "memory");
}
__device__ __forceinline__ void dsmem_push(uint32_t dst, uint32_t src, uint32_t bytes, uint32_t rmbar) {
    asm volatile(
        "cp.async.bulk.shared::cluster.shared::cta.mbarrier::complete_tx::bytes [%0], [%1], %2, [%3];"
        :: "r"(dst), "r"(src), "r"(bytes), "r"(rmbar) : "memory");
}

#define GEMM8(hA, hB, wv)                                              \
    {   u64 w0 = pack2((wv).x, (wv).x), w1 = pack2((wv).y, (wv).y);    \
        a00 = ffma2((hA).x, w0, a00); a01 = ffma2((hA).x, w1, a01);    \
        a10 = ffma2((hA).y, w0, a10); a11 = ffma2((hA).y, w1, a11);    \
        a20 = ffma2((hB).x, w0, a20); a21 = ffma2((hB).x, w1, a21);    \
        a30 = ffma2((hB).y, w0, a30); a31 = ffma2((hB).y, w1, a31); }

__global__ __launch_bounds__(NT, 1) __cluster_dims__(8, 1, 1)
void ron_kernel(const float* __restrict__ x, const float* __restrict__ x2h,
                const float* __restrict__ h2h, const float* __restrict__ bias,
                const float* __restrict__ gam, const float* __restrict__ eps,
                float* __restrict__ out, long long out_elems)
{
    extern __shared__ char smem[];
    float* W  = (float*)smem;                 // [576][64] global-k order (512..575 = x2h)
    float* vb = (float*)(smem + VB_OFF);      // [2][512][8] hy by global h index
    float* xb = (float*)(smem + XB_OFF);      // [64][8]
    float* rf = (float*)(smem + RF_OFF);      // [8][8][64]
    const uint32_t sbase = smem_u32(smem);
    const uint32_t mbarA = sbase + MBA_OFF;
    const uint32_t mbarB = sbase + MBB_OFF;

    const int tid  = threadIdx.x;
    const int cl   = blockIdx.x >> 3;
    const int rank = blockIdx.x & 7;
    const int c0   = rank * 64;
    const int b0   = cl * 8;

    // prologue: resident weight slice
    for (int idx = tid; idx < 576*64; idx += NT) {
        int k = idx >> 6, j = idx & 63;
        W[idx] = (k < Hn) ? h2h[(size_t)k*Hn + c0 + j] : x2h[(size_t)(k - Hn)*Hn + c0 + j];
    }

    // epilogue mapping: thread owns (b4, col) and (b4+4, col)
    const int col = tid & 63, b4 = tid >> 6;      // b4 in 0..3
    const int hg  = c0 + col;
    const float bia = bias[hg], ga = gam[hg], ep = eps[hg];
    float hy0 = 0.f, hz0 = 0.f, hy1 = 0.f, hz1 = 0.f;

    // GEMM mapping: warp w 0..7, lane cg owns cols {2cg, 2cg+1}
    const int w  = tid >> 5, cg = tid & 31;
    const int wrow1 = (w < 4) ? (c0 + w*16) : (512 + (w - 4)*16);   // pass1 W rows
    const float* Wr1 = W + wrow1*64 + cg*2;
    float*       rw  = rf + w*512 + cg*2;

    // pusher setup: warps 1..7, lane 0 pushes the CTA slice to rank+w
    const int dstRank = (rank + w) & 7;
    const uint32_t pushDstV = mapa_u32(sbase + VB_OFF, dstRank);     // + buf + c0*32 at use
    const uint32_t pushDstM = mapa_u32((w <= 3) ? mbarA : mbarB, dstRank);

    // x pointers
    const float* xp0 = x + ((size_t)(b0 + b4)     * Tn) * In + col;
    const float* xp1 = x + ((size_t)(b0 + b4 + 4) * Tn) * In + col;

    // init: own rows of vb[1] (read by pass1 at t=0) zero; stage x(0); mbarriers
    vb[4096 + hg*8 + b4]     = 0.f;
    vb[4096 + hg*8 + b4 + 4] = 0.f;
    xb[col*8 + b4]     = xp0[0];
    xb[col*8 + b4 + 4] = xp1[0];
    if (tid == 0) { mbar_init(mbarA, 1); mbar_init(mbarB, 1); }
    __syncthreads();
    asm volatile("barrier.cluster.arrive.aligned;" ::: "memory");
    asm volatile("barrier.cluster.wait.aligned;"   ::: "memory");
    if (tid == 0) { mbar_expect(mbarA, TXA); mbar_expect(mbarB, TXB); }  // phase 0

    const size_t BTH = (size_t)Bn * Tn * Hn;
    const bool writeFinal = (out_elems >= (long long)(BTH + (size_t)Bn * Hn));

    for (int t = 0; t < Tn; t++) {
        const float* vprev = vb + ((t - 1) & 1) * 4096;
        const int tn = (t + 1 < Tn) ? (t + 1) : t;
        const float xn0 = xp0[(size_t)tn * In];    // prefetch x(t+1)
        const float xn1 = xp1[(size_t)tn * In];

        u64 a00=0ull,a01=0ull,a10=0ull,a11=0ull,a20=0ull,a21=0ull,a30=0ull,a31=0ull;

        // ---- pass1: local k (own 64 hy rows + 64 x rows), hides arrival of group A
        {
            const float* vr1 = (w < 4) ? (vprev + (c0 + w*16)*8) : (xb + (w - 4)*16*8);
            #pragma unroll 4
            for (int kk = 0; kk < 16; kk++) {
                float2 wv = *(const float2*)(Wr1 + kk*64);
                const ulonglong2* hv = (const ulonglong2*)(vr1 + kk*8);
                ulonglong2 hA = hv[0];
                ulonglong2 hB = hv[1];
                GEMM8(hA, hB, wv);
            }
        }

        if (t > 0) {
            // ---- group A: earliest-arriving 3 peer slices (sources rank-1..rank-3)
            mbar_wait(mbarA, (t - 1) & 1);
            if (t < Tn - 1 && tid == 0) mbar_expect(mbarA, TXA);
            #pragma unroll
            for (int j = 1; j <= 3; j++) {
                int s = (rank - j) & 7;
                const float* Wr = W     + (s*64 + w*8)*64 + cg*2;
                const float* vr = vprev + (s*64 + w*8)*8;
                #pragma unroll
                for (int kk = 0; kk < 8; kk++) {
                    float2 wv = *(const float2*)(Wr + kk*64);
                    const ulonglong2* hv = (const ulonglong2*)(vr + kk*8);
                    ulonglong2 hA = hv[0];
                    ulonglong2 hB = hv[1];
                    GEMM8(hA, hB, wv);
                }
            }
            // ---- group B: remaining 4 peer slices (their wait hidden behind group A GEMM)
            mbar_wait(mbarB, (t - 1) & 1);
            if (t < Tn - 1 && tid == 0) mbar_expect(mbarB, TXB);
            #pragma unroll
            for (int j = 4; j <= 7; j++) {
                int s = (rank - j) & 7;
                const float* Wr = W     + (s*64 + w*8)*64 + cg*2;
                const float* vr = vprev + (s*64 + w*8)*8;
                #pragma unroll
                for (int kk = 0; kk < 8; kk++) {
                    float2 wv = *(const float2*)(Wr + kk*64);
                    const ulonglong2* hv = (const ulonglong2*)(vr + kk*8);
                    ulonglong2 hA = hv[0];
                    ulonglong2 hB = hv[1];
                    GEMM8(hA, hB, wv);
                }
            }
        }

        // ---- stage split-K partials [w][b][col]
        {
            float l0,h0,l1,h1;
            unpack2(a00,l0,h0); unpack2(a01,l1,h1);
            *(float2*)(rw + 0*64) = make_float2(l0,l1);
            *(float2*)(rw + 1*64) = make_float2(h0,h1);
            unpack2(a10,l0,h0); unpack2(a11,l1,h1);
            *(float2*)(rw + 2*64) = make_float2(l0,l1);
            *(float2*)(rw + 3*64) = make_float2(h0,h1);
            unpack2(a20,l0,h0); unpack2(a21,l1,h1);
            *(float2*)(rw + 4*64) = make_float2(l0,l1);
            *(float2*)(rw + 5*64) = make_float2(h0,h1);
            unpack2(a30,l0,h0); unpack2(a31,l1,h1);
            *(float2*)(rw + 6*64) = make_float2(l0,l1);
            *(float2*)(rw + 7*64) = make_float2(h0,h1);
        }
        __syncthreads();

        // ---- reduce + oscillator update (state only; global stores deferred past sync2)
        {
            float s0 = 0.f, s1 = 0.f;
            const float* r0 = rf + b4*64 + col;
            const float* r1 = r0 + 4*64;
            #pragma unroll
            for (int q = 0; q < 8; q++) { s0 += r0[q*512]; s1 += r1[q*512]; }
            float th0 = tanhf(s0 + bia);
            float th1 = tanhf(s1 + bia);
            hz0 += DTc * (th0 - ga*hy0 - ep*hz0);  hy0 += DTc * hz0;
            hz1 += DTc * (th1 - ga*hy1 - ep*hz1);  hy1 += DTc * hz1;

            // own slice into vb[t&1] (pushed to peers below) + stage x(t+1)
            float* vnext = vb + (t & 1)*4096;
            vnext[hg*8 + b4]     = hy0;
            vnext[hg*8 + b4 + 4] = hy1;
            xb[col*8 + b4]     = xn0;
            xb[col*8 + b4 + 4] = xn1;
        }
        __syncthreads();   // own-slice STS drained; rf/xb reads done

        // ---- push own 2KB slice: warps 1..7 each push to rank+w (parallel engine queue)
        if (t < Tn - 1 && cg == 0 && w >= 1) {
            asm volatile("fence.proxy.async.shared::cta;" ::: "memory");
            uint32_t srcOff = (uint32_t)((t & 1)*16384 + c0*32);
            dsmem_push(pushDstV + srcOff, sbase + VB_OFF + srcOff, SLICE_BYTES, pushDstM);
        }

        // ---- deferred global stores (off the exchange critical path)
        {
            size_t o0 = ((size_t)(b0 + b4) * Tn + t) * Hn + hg;
            out[o0]                       = hy0;
            out[o0 + (size_t)4 * Tn * Hn] = hy1;
            if (t == Tn - 1 && writeFinal) {
                out[BTH + (size_t)(b0 + b4)     * Hn + hg] = hy0;
                out[BTH + (size_t)(b0 + b4 + 4) * Hn + hg] = hy1;
            }
        }
    }

    asm volatile("barrier.cluster.arrive.aligned;" ::: "memory");
    asm volatile("barrier.cluster.wait.aligned;"   ::: "memory");
}

extern "C" void kernel_launch(void* const* d_in, const int* in_sizes, int n_in,
                              void* d_out, int out_size) {
    const float* x    = (const float*)d_in[0];
    const float* x2h  = (const float*)d_in[1];
    const float* h2h  = (const float*)d_in[2];
    const float* bias = (const float*)d_in[3];
    const float* gam  = (const float*)d_in[4];
    const float* eps  = (const float*)d_in[5];
    float* out = (float*)d_out;
    (void)in_sizes; (void)n_in;

    cudaFuncSetAttribute(ron_kernel, cudaFuncAttributeMaxDynamicSharedMemorySize, SMEM_BYTES);
    ron_kernel<<<128, NT, SMEM_BYTES>>>(x, x2h, h2h, bias, gam, eps, out, (long long)out_size);
}